// round 1
// baseline (speedup 1.0000x reference)
#include <cuda_runtime.h>
#include <math.h>

#define TLEN 1024
#define BATCH 64
#define INFV 1e30f

// Per-batch path losses (scratch; no allocations allowed, so __device__ global).
__device__ float g_losses[BATCH];

// One block per batch. Thread i owns row i. Anti-diagonal wavefront over the
// 1024x1024 DTW table. We carry TWO DP values per cell:
//   C[i,j] = D2(i,j) + min(C[i-1,j], C[i,j-1], C[i-1,j-1])   (L2 point dist)
//   L[i,j] = L1w(i,j) + L[parent(i,j)]
// where parent = argmin with first-min tie order (diag, up, left) — exactly
// the backtrace rule in the reference. Then loss_b = L[T-1,T-1], which equals
// the backtraced path sum, so no backtrace / decision storage is needed.
__global__ void __launch_bounds__(TLEN, 1)
dtw_loss_kernel(const float* __restrict__ preds,
                const float* __restrict__ targs,
                const float* __restrict__ subcoef)
{
    __shared__ float px[TLEN], py[TLEN], qx[TLEN], qy[TLEN];
    __shared__ float cbuf[3][TLEN];   // rotating diagonals of C
    __shared__ float lbuf[3][TLEN];   // rotating diagonals of L

    const int b = blockIdx.x;
    const int i = threadIdx.x;

    const float* P = preds + (size_t)b * TLEN * 4;
    const float* Q = targs + (size_t)b * TLEN * 4;

    px[i] = P[i * 4 + 0];
    py[i] = P[i * 4 + 1];
    qx[i] = Q[i * 4 + 0];
    qy[i] = Q[i * 4 + 1];
    const float sc0 = subcoef[0];
    const float sc1 = subcoef[1];
    __syncthreads();

    const float mypx = px[i];
    const float mypy = py[i];

    // Rotating buffer indices: at diagonal d we write w, read r1 (=d-1), r2 (=d-2).
    int w = 0, r1 = 2, r2 = 1;

    for (int d = 0; d < 2 * TLEN - 1; ++d) {
        const int j = d - i;
        if (j >= 0 && j < TLEN) {
            const float dx = mypx - qx[j];
            const float dy = mypy - qy[j];
            const float Dij = sqrtf(dx * dx + dy * dy);

            const bool gi = (i > 0);
            const bool gj = (j > 0);
            const float cd = (gi && gj) ? cbuf[r2][i - 1] : INFV; // C[i-1,j-1]
            const float cu = gi         ? cbuf[r1][i - 1] : INFV; // C[i-1,j]
            const float cl = gj         ? cbuf[r1][i]     : INFV; // C[i,j-1]

            float Cv, Lp;
            if (d == 0) {
                Cv = Dij;       // C[0,0] = D[0,0]
                Lp = 0.0f;      // path starts here
            } else {
                const float m = fminf(cd, fminf(cu, cl));
                Cv = Dij + m;
                // argmin with first-occurrence tie-break: order (diag, up, left)
                if (cd <= cu && cd <= cl)      Lp = lbuf[r2][i - 1];
                else if (cu <= cl)             Lp = lbuf[r1][i - 1];
                else                           Lp = lbuf[r1][i];
            }
            const float l1c = fabsf(dx) * sc0 + fabsf(dy) * sc1;
            const float Lv = l1c + Lp;

            cbuf[w][i] = Cv;
            lbuf[w][i] = Lv;

            if (d == 2 * TLEN - 2) {          // only (i,j)=(T-1,T-1) reaches here
                g_losses[b] = Lv;
            }
        }
        __syncthreads();
        // rotate: w -> r1 -> r2 -> w
        const int t = r2;
        r2 = r1;
        r1 = w;
        w = t;
    }
}

// Deterministic fixed-order reduction of the 64 per-batch losses.
__global__ void dtw_reduce_kernel(float* __restrict__ out)
{
    float s = 0.0f;
#pragma unroll
    for (int b = 0; b < BATCH; ++b) s += g_losses[b];
    out[0] = s;
}

extern "C" void kernel_launch(void* const* d_in, const int* in_sizes, int n_in,
                              void* d_out, int out_size)
{
    const float* preds   = (const float*)d_in[0];
    const float* targs   = (const float*)d_in[1];
    const float* subcoef = (const float*)d_in[2];
    float* out = (float*)d_out;
    (void)in_sizes; (void)n_in; (void)out_size;

    dtw_loss_kernel<<<BATCH, TLEN>>>(preds, targs, subcoef);
    dtw_reduce_kernel<<<1, 1>>>(out);
}

// round 2
// speedup vs baseline: 3.0216x; 3.0216x over previous
#include <cuda_runtime.h>

#define TLEN 1024
#define BATCH 64
#define NTH   128          // threads per block (4 warps = 1 per SMSP)
#define RPT   8            // rows per thread (NTH * RPT == TLEN)
#define INFV  1e30f

// Per-batch path losses (no allocs allowed -> __device__ global scratch).
__device__ float g_losses[BATCH];

__device__ __forceinline__ float rsqrt_approx(float x) {
    float r;
    asm("rsqrt.approx.f32 %0, %1;" : "=f"(r) : "f"(x));
    return r;
}

// One block per batch. Thread t owns rows [t*RPT, t*RPT+RPT). Wavefront over
// columns: at step s, thread t processes column c = s - t, computing its 8-row
// strip sequentially in registers. Cross-thread dependency is only the bottom
// row of thread t-1 (columns c and c-1), carried through a double-buffered
// shared boundary plus a 1-step register lag. We carry two DP values:
//   C[i,j] = D(i,j) + min(C[i-1,j-1], C[i-1,j], C[i,j-1])   (L2 point dist)
//   L[i,j] = L1w(i,j) + L[parent(i,j)]
// with parent = first-min argmin in order (diag, up, left) — exactly the
// reference backtrace rule — so loss_b = L[T-1,T-1] with no backtrace pass.
__global__ void __launch_bounds__(NTH, 1)
dtw_loss_kernel(const float* __restrict__ preds,
                const float* __restrict__ targs,
                const float* __restrict__ subcoef)
{
    __shared__ float2 qs[TLEN];        // target (x, y) per column
    __shared__ float2 bnd[2][NTH];     // (C, L) bottom-row boundary, dbl-buffered

    const int b = blockIdx.x;
    const int t = threadIdx.x;
    const float* P = preds + (size_t)b * TLEN * 4;
    const float* Q = targs + (size_t)b * TLEN * 4;

    for (int c = t; c < TLEN; c += NTH)
        qs[c] = make_float2(Q[c * 4 + 0], Q[c * 4 + 1]);

    float pxr[RPT], pyr[RPT];
    const int rb = t * RPT;
#pragma unroll
    for (int r = 0; r < RPT; r++) {
        pxr[r] = P[(rb + r) * 4 + 0];
        pyr[r] = P[(rb + r) * 4 + 1];
    }
    const float sc0 = subcoef[0];
    const float sc1 = subcoef[1];

    // Left-column state (column c-1) per owned row.
    float Cl[RPT], Ll[RPT];
#pragma unroll
    for (int r = 0; r < RPT; r++) { Cl[r] = INFV; Ll[r] = 0.0f; }

    float bCp = INFV, bLp = 0.0f;      // boundary diag lag (column c-1)

    __syncthreads();

    const int NSTEP = TLEN + NTH - 1;
    for (int s = 0; s < NSTEP; s++) {
        const int c = s - t;
        if (c >= 0 && c < TLEN) {
            const float2 qc = qs[c];

            float bC, bL;
            if (t > 0) {
                float2 v = bnd[s & 1][t - 1];   // thread t-1 bottom row, column c
                bC = v.x; bL = v.y;
            } else {
                bC = INFV; bL = 0.0f;
            }

            const bool origin = ((t | c) == 0);  // cell (0,0) lives in r==0 of thread 0
            float up = bC, upL = bL, dg = bCp, dgL = bLp;

#pragma unroll
            for (int r = 0; r < RPT; r++) {
                const float dx = pxr[r] - qc.x;
                const float dy = pyr[r] - qc.y;
                float s2 = fmaf(dx, dx, 1e-35f);
                s2 = fmaf(dy, dy, s2);
                const float D = s2 * rsqrt_approx(s2);

                const float lf = Cl[r], lfL = Ll[r];
                // 3-way min, tie order (diag, up, left) == reference argmin
                const float m1  = fminf(dg, up);
                const float m1L = (dg <= up) ? dgL : upL;
                float m   = fminf(m1, lf);
                float Lp  = (m1 <= lf) ? m1L : lfL;
                if (r == 0 && origin) { m = 0.0f; Lp = 0.0f; }  // C[0,0] = D[0,0]

                const float Cv = D + m;
                const float l1 = fmaf(fabsf(dy), sc1, fabsf(dx) * sc0);
                const float Lv = l1 + Lp;

                dg = lf; dgL = lfL;      // diag for next row = old left of this row
                up = Cv; upL = Lv;       // up   for next row = this cell
                Cl[r] = Cv; Ll[r] = Lv;
            }

            bCp = bC; bLp = bL;          // lag boundary (becomes column c-1)
            bnd[(s + 1) & 1][t] = make_float2(Cl[RPT - 1], Ll[RPT - 1]);

            if (t == NTH - 1 && c == TLEN - 1)
                g_losses[b] = Ll[RPT - 1];
        }
        __syncthreads();
    }
}

// Deterministic fixed-order reduction of per-batch losses.
__global__ void dtw_reduce_kernel(float* __restrict__ out)
{
    float s = 0.0f;
#pragma unroll
    for (int b = 0; b < BATCH; ++b) s += g_losses[b];
    out[0] = s;
}

extern "C" void kernel_launch(void* const* d_in, const int* in_sizes, int n_in,
                              void* d_out, int out_size)
{
    const float* preds   = (const float*)d_in[0];
    const float* targs   = (const float*)d_in[1];
    const float* subcoef = (const float*)d_in[2];
    float* out = (float*)d_out;
    (void)in_sizes; (void)n_in; (void)out_size;

    dtw_loss_kernel<<<BATCH, NTH>>>(preds, targs, subcoef);
    dtw_reduce_kernel<<<1, 1>>>(out);
}